// round 15
// baseline (speedup 1.0000x reference)
#include <cuda_runtime.h>
#include <cuda_bf16.h>

// CrossHeadOnlineHadamardHook: 32-point Walsh-Hadamard across heads.
// x: (T, 4096) fp32 rows, T = 16384. heads = 32, HEAD_DIM = 128.
// For each (t, d): v[h] = x[t*4096 + h*128 + d], v = H32 * v / sqrt(32).
//
// FINAL KERNEL — 3x reproduced best (82.11 / 82.08 / 82.02 us,
// 6.22-6.26 TB/s HBM). 536 MB read+write traffic is irreducible for an
// out-of-place fp32 transform; 6.23 TB/s is this chip's measured mixed
// read/write HBM ceiling (confirmed invariant across f2/f4, .cs/.ca,
// 12/24 warps per SM), so the kernel sits at the roofline: 86.7% of
// the 67us spec-bandwidth floor.
//
// Structure: one thread owns one (token, d-quad).
//   - 32 front-batched coalesced LDG.128 (512B/warp; each warp sweeps a
//     16KB contiguous token row), evict-first (__ldcs) — read-once data.
//   - In-register 32-point FWHT over 4 independent fp32 lanes
//     (natural-order Sylvester H32). rel_err 0.0 vs reference.
//   - 32 coalesced STG.128, evict-first (__stcs) — write-once data.
//
// Config is load-bearing (every alternative measured):
//   - 128-thread blocks: 154 regs -> 3 CTAs/SM = 12 warps, the minimum
//     saturating DRAM request depth (256-thr -> 1 CTA/SM -> -9%).
//   - Non-persistent 4096-CTA grid: HW wave scheduling overlaps CTA
//     prologues; grid-stride looping serializes loads behind stores (-10%).
//   - Continuous mixed R/W beats smem phase-split bursts (-12%).
//   - __stcs stores beat __stwt write-through (-2%).
//   - Forcing 4 CTAs/SM would spill (32 float4 = 128 data regs): rejected.

#define NUM_HEADS 32
#define HEAD_DIM  128
#define HIDDEN    (NUM_HEADS * HEAD_DIM)      // 4096
#define QUADS_PER_ROW (HIDDEN / 4)            // 1024 float4 per token row
#define HQUAD_STRIDE (HEAD_DIM / 4)           // 32 float4 between heads
#define THREADS 128

__global__ __launch_bounds__(THREADS)
void had32_crosshead_f4_kernel(const float4* __restrict__ x,
                               float4* __restrict__ out,
                               int n_items_total)
{
    int item = blockIdx.x * THREADS + threadIdx.x;
    if (item >= n_items_total) return;

    int t = item >> 5;          // token index (32 quads per token)
    int q = item & 31;          // which float4 within the head dim

    size_t base = (size_t)t * QUADS_PER_ROW + q;
    const float4* __restrict__ px = x + base;
    float4*       __restrict__ py = out + base;

    float4 v[NUM_HEADS];

    // 32 coalesced LDG.128 (512B/warp), evict-first streaming
#pragma unroll
    for (int h = 0; h < NUM_HEADS; ++h) {
        v[h] = __ldcs(px + (size_t)h * HQUAD_STRIDE);
    }

    // In-register 32-point FWHT over 4 independent lanes
#pragma unroll
    for (int s = 1; s < NUM_HEADS; s <<= 1) {
#pragma unroll
        for (int i = 0; i < NUM_HEADS; ++i) {
            if ((i & s) == 0) {
                float4 a = v[i];
                float4 b = v[i + s];
                v[i].x     = a.x + b.x;
                v[i].y     = a.y + b.y;
                v[i].z     = a.z + b.z;
                v[i].w     = a.w + b.w;
                v[i + s].x = a.x - b.x;
                v[i + s].y = a.y - b.y;
                v[i + s].z = a.z - b.z;
                v[i + s].w = a.w - b.w;
            }
        }
    }

    const float scl = 0.17677669529663687f;   // 1/sqrt(32)

    // 32 coalesced STG.128, evict-first
#pragma unroll
    for (int h = 0; h < NUM_HEADS; ++h) {
        float4 r;
        r.x = v[h].x * scl;
        r.y = v[h].y * scl;
        r.z = v[h].z * scl;
        r.w = v[h].w * scl;
        __stcs(py + (size_t)h * HQUAD_STRIDE, r);
    }
}

extern "C" void kernel_launch(void* const* d_in, const int* in_sizes, int n_in,
                              void* d_out, int out_size)
{
    const float4* x = (const float4*)d_in[0];
    float4* out = (float4*)d_out;

    int n = in_sizes[0];                 // total fp32 elements (4*4096*4096)
    int n_items = n >> 7;                // one item = quad x 32 heads = 128 floats
    int blocks = (n_items + THREADS - 1) / THREADS;

    had32_crosshead_f4_kernel<<<blocks, THREADS>>>(x, out, n_items);
}

// round 16
// speedup vs baseline: 1.0031x; 1.0031x over previous
#include <cuda_runtime.h>
#include <cuda_bf16.h>

// CrossHeadOnlineHadamardHook: 32-point Walsh-Hadamard across heads.
// x: (T, 4096) fp32 rows, T = 16384. heads = 32, HEAD_DIM = 128.
// For each (t, d): v[h] = x[t*4096 + h*128 + d], v = H32 * v / sqrt(32).
//
// FINAL KERNEL — 4x reproduced best (82.11 / 82.08 / 82.02 / 82.66 us;
// run-to-run noise ~±0.4us on identical binary). 6.22-6.27 TB/s HBM =
// this chip's measured mixed read/write ceiling; 536 MB traffic is
// irreducible for an out-of-place fp32 transform, so the kernel sits at
// the roofline (ncu 76.6us = 87% of the 67us spec-bandwidth floor).
//
// Structure: one thread owns one (token, d-quad).
//   - 32 front-batched coalesced LDG.128 (512B/warp; each warp sweeps a
//     16KB contiguous token row), evict-first (__ldcs) — read-once data.
//   - In-register 32-point FWHT over 4 independent fp32 lanes
//     (natural-order Sylvester H32). rel_err 0.0 vs reference.
//   - 32 coalesced STG.128, evict-first (__stcs) — write-once data.
//
// Config is load-bearing (every alternative measured):
//   - 128-thread blocks: 154 regs -> 3 CTAs/SM = 12 warps, the minimum
//     saturating DRAM request depth (256-thr -> 1 CTA/SM -> -9%).
//     Occupancy is flat 12..24 warps/SM (f2 variant), so higher-occ
//     shuffle-split variants target a non-binding resource.
//   - Non-persistent 4096-CTA grid: HW wave scheduling overlaps CTA
//     prologues; grid-stride looping serializes loads behind stores (-10%).
//   - Continuous mixed R/W beats smem phase-split bursts (-12%).
//   - __stcs stores beat __stwt write-through (-2%).

#define NUM_HEADS 32
#define HEAD_DIM  128
#define HIDDEN    (NUM_HEADS * HEAD_DIM)      // 4096
#define QUADS_PER_ROW (HIDDEN / 4)            // 1024 float4 per token row
#define HQUAD_STRIDE (HEAD_DIM / 4)           // 32 float4 between heads
#define THREADS 128

__global__ __launch_bounds__(THREADS)
void had32_crosshead_f4_kernel(const float4* __restrict__ x,
                               float4* __restrict__ out,
                               int n_items_total)
{
    int item = blockIdx.x * THREADS + threadIdx.x;
    if (item >= n_items_total) return;

    int t = item >> 5;          // token index (32 quads per token)
    int q = item & 31;          // which float4 within the head dim

    size_t base = (size_t)t * QUADS_PER_ROW + q;
    const float4* __restrict__ px = x + base;
    float4*       __restrict__ py = out + base;

    float4 v[NUM_HEADS];

    // 32 coalesced LDG.128 (512B/warp), evict-first streaming
#pragma unroll
    for (int h = 0; h < NUM_HEADS; ++h) {
        v[h] = __ldcs(px + (size_t)h * HQUAD_STRIDE);
    }

    // In-register 32-point FWHT over 4 independent lanes
#pragma unroll
    for (int s = 1; s < NUM_HEADS; s <<= 1) {
#pragma unroll
        for (int i = 0; i < NUM_HEADS; ++i) {
            if ((i & s) == 0) {
                float4 a = v[i];
                float4 b = v[i + s];
                v[i].x     = a.x + b.x;
                v[i].y     = a.y + b.y;
                v[i].z     = a.z + b.z;
                v[i].w     = a.w + b.w;
                v[i + s].x = a.x - b.x;
                v[i + s].y = a.y - b.y;
                v[i + s].z = a.z - b.z;
                v[i + s].w = a.w - b.w;
            }
        }
    }

    const float scl = 0.17677669529663687f;   // 1/sqrt(32)

    // 32 coalesced STG.128, evict-first
#pragma unroll
    for (int h = 0; h < NUM_HEADS; ++h) {
        float4 r;
        r.x = v[h].x * scl;
        r.y = v[h].y * scl;
        r.z = v[h].z * scl;
        r.w = v[h].w * scl;
        __stcs(py + (size_t)h * HQUAD_STRIDE, r);
    }
}

extern "C" void kernel_launch(void* const* d_in, const int* in_sizes, int n_in,
                              void* d_out, int out_size)
{
    const float4* x = (const float4*)d_in[0];
    float4* out = (float4*)d_out;

    int n = in_sizes[0];                 // total fp32 elements (4*4096*4096)
    int n_items = n >> 7;                // one item = quad x 32 heads = 128 floats
    int blocks = (n_items + THREADS - 1) / THREADS;

    had32_crosshead_f4_kernel<<<blocks, THREADS>>>(x, out, n_items);
}

// round 17
// speedup vs baseline: 1.0058x; 1.0027x over previous
#include <cuda_runtime.h>
#include <cuda_bf16.h>

// CrossHeadOnlineHadamardHook: 32-point Walsh-Hadamard across heads.
// x: (T, 4096) fp32 rows, T = 16384. heads = 32, HEAD_DIM = 128.
// For each (t, d): v[h] = x[t*4096 + h*128 + d], v = H32 * v / sqrt(32).
//
// R16 probe — final unmeasured config cell: 96-thread blocks.
// 160 regs x 96 thr -> 4 CTAs/SM x 3 warps = same 12 warps/SM as the
// 5x-reproduced 128-thr winner (82.0-82.7us, 6.22-6.27 TB/s = chip's
// mixed R/W HBM ceiling), but 4 independent CTA load-burst streams per
// SM instead of 3 and finer tail quantization (grid 5462). Everything
// else identical: per-thread float4 item, 32 front-batched coalesced
// LDG.128 evict-first, register FWHT, 32 coalesced STG.128 evict-first.
// Predicted neutral; decision rule: best measured config becomes the
// permanent final kernel.
//
// Measured & ruled out: smem phase-split (-12%), persistent grid (-10%),
// 256-thr/8 warps (-9%), __stwt stores (-2%), f2/cache-policy variants
// (neutral at the same bandwidth ceiling).

#define NUM_HEADS 32
#define HEAD_DIM  128
#define HIDDEN    (NUM_HEADS * HEAD_DIM)      // 4096
#define QUADS_PER_ROW (HIDDEN / 4)            // 1024 float4 per token row
#define HQUAD_STRIDE (HEAD_DIM / 4)           // 32 float4 between heads
#define THREADS 96

__global__ __launch_bounds__(THREADS)
void had32_crosshead_f4_kernel(const float4* __restrict__ x,
                               float4* __restrict__ out,
                               int n_items_total)
{
    int item = blockIdx.x * THREADS + threadIdx.x;
    if (item >= n_items_total) return;

    int t = item >> 5;          // token index (32 quads per token)
    int q = item & 31;          // which float4 within the head dim

    size_t base = (size_t)t * QUADS_PER_ROW + q;
    const float4* __restrict__ px = x + base;
    float4*       __restrict__ py = out + base;

    float4 v[NUM_HEADS];

    // 32 coalesced LDG.128 (512B/warp), evict-first streaming
#pragma unroll
    for (int h = 0; h < NUM_HEADS; ++h) {
        v[h] = __ldcs(px + (size_t)h * HQUAD_STRIDE);
    }

    // In-register 32-point FWHT over 4 independent lanes
#pragma unroll
    for (int s = 1; s < NUM_HEADS; s <<= 1) {
#pragma unroll
        for (int i = 0; i < NUM_HEADS; ++i) {
            if ((i & s) == 0) {
                float4 a = v[i];
                float4 b = v[i + s];
                v[i].x     = a.x + b.x;
                v[i].y     = a.y + b.y;
                v[i].z     = a.z + b.z;
                v[i].w     = a.w + b.w;
                v[i + s].x = a.x - b.x;
                v[i + s].y = a.y - b.y;
                v[i + s].z = a.z - b.z;
                v[i + s].w = a.w - b.w;
            }
        }
    }

    const float scl = 0.17677669529663687f;   // 1/sqrt(32)

    // 32 coalesced STG.128, evict-first
#pragma unroll
    for (int h = 0; h < NUM_HEADS; ++h) {
        float4 r;
        r.x = v[h].x * scl;
        r.y = v[h].y * scl;
        r.z = v[h].z * scl;
        r.w = v[h].w * scl;
        __stcs(py + (size_t)h * HQUAD_STRIDE, r);
    }
}

extern "C" void kernel_launch(void* const* d_in, const int* in_sizes, int n_in,
                              void* d_out, int out_size)
{
    const float4* x = (const float4*)d_in[0];
    float4* out = (float4*)d_out;

    int n = in_sizes[0];                 // total fp32 elements (4*4096*4096)
    int n_items = n >> 7;                // one item = quad x 32 heads = 128 floats
    int blocks = (n_items + THREADS - 1) / THREADS;

    had32_crosshead_f4_kernel<<<blocks, THREADS>>>(x, out, n_items);
}